// round 1
// baseline (speedup 1.0000x reference)
#include <cuda_runtime.h>
#include <cuda_bf16.h>
#include <math.h>

// Problem constants
#define BATCH   4
#define SEQ     2048
#define DMODEL  1024
#define NHEADS  16
#define DHEAD   64
#define MROWS   (BATCH * SEQ)         // 8192
#define NBH     (BATCH * NHEADS)      // 64
#define QSCALE  0.125f                // 1/sqrt(64)

// ---------------- scratch (static device allocations; no runtime alloc) -----
__device__ float d_qbuf[NBH * SEQ * DHEAD];   // [bh][t][d]  32MB
__device__ float d_kbuf[NBH * SEQ * DHEAD];
__device__ float d_vbuf[NBH * SEQ * DHEAD];
__device__ float d_gbuf[NBH * SEQ];           // [bh][t]
__device__ float d_ybuf[MROWS * DMODEL];      // [m][n] row-major, n = h*64+d

// ---------------- SGEMM:  C = X @ W^T,  X [8192,1024], W [1024,1024] --------
// BM=128 BN=128 BK=8, 256 threads, 8x8 micro-tile.
// MODE 0: q proj  -> phi(c*QSCALE) scattered to d_qbuf
// MODE 1: k proj  -> phi(c)        scattered to d_kbuf
// MODE 2: v proj  -> c             scattered to d_vbuf
// MODE 3: out proj: A = d_ybuf, plain write to Cout
#define BM 128
#define BN 128
#define BK 8

__device__ __forceinline__ float phi(float x) {
    // elu(x)+1
    return x > 0.0f ? x + 1.0f : __expf(x);
}

template<int MODE>
__global__ __launch_bounds__(256) void sgemm_kernel(const float* __restrict__ X,
                                                    const float* __restrict__ W,
                                                    float* __restrict__ Cout) {
    const float* A = (MODE == 3) ? d_ybuf : X;

    __shared__ float As[BK][BM];
    __shared__ float Bs[BK][BN];

    const int bm = blockIdx.y * BM;
    const int bn = blockIdx.x * BN;
    const int tid = threadIdx.x;

    const int arow = tid >> 1;          // 0..127
    const int acol = (tid & 1) * 4;     // 0 or 4
    const int tr = tid >> 4;            // 0..15
    const int tc = tid & 15;            // 0..15

    const float* Aptr = A + (size_t)(bm + arow) * DMODEL + acol;
    const float* Wptr = W + (size_t)(bn + arow) * DMODEL + acol;

    float acc[8][8];
#pragma unroll
    for (int i = 0; i < 8; i++)
#pragma unroll
        for (int j = 0; j < 8; j++) acc[i][j] = 0.0f;

    for (int k0 = 0; k0 < DMODEL; k0 += BK) {
        float4 av = *(const float4*)(Aptr + k0);
        float4 wv = *(const float4*)(Wptr + k0);
        As[acol + 0][arow] = av.x;
        As[acol + 1][arow] = av.y;
        As[acol + 2][arow] = av.z;
        As[acol + 3][arow] = av.w;
        Bs[acol + 0][arow] = wv.x;
        Bs[acol + 1][arow] = wv.y;
        Bs[acol + 2][arow] = wv.z;
        Bs[acol + 3][arow] = wv.w;
        __syncthreads();

#pragma unroll
        for (int k = 0; k < BK; k++) {
            float4 a0 = *(const float4*)&As[k][tr * 8];
            float4 a1 = *(const float4*)&As[k][tr * 8 + 4];
            float4 b0 = *(const float4*)&Bs[k][tc * 8];
            float4 b1 = *(const float4*)&Bs[k][tc * 8 + 4];
            float af[8] = {a0.x, a0.y, a0.z, a0.w, a1.x, a1.y, a1.z, a1.w};
            float bf[8] = {b0.x, b0.y, b0.z, b0.w, b1.x, b1.y, b1.z, b1.w};
#pragma unroll
            for (int i = 0; i < 8; i++)
#pragma unroll
                for (int j = 0; j < 8; j++)
                    acc[i][j] = fmaf(af[i], bf[j], acc[i][j]);
        }
        __syncthreads();
    }

    // epilogue
#pragma unroll
    for (int i = 0; i < 8; i++) {
        const int m = bm + tr * 8 + i;
#pragma unroll
        for (int j = 0; j < 8; j++) {
            const int n = bn + tc * 8 + j;
            float c = acc[i][j];
            if (MODE == 3) {
                Cout[(size_t)m * DMODEL + n] = c;
            } else {
                const int b = m >> 11;          // m / 2048
                const int t = m & 2047;
                const int h = n >> 6;
                const int d = n & 63;
                const size_t idx = ((size_t)(b * NHEADS + h) * SEQ + t) * DHEAD + d;
                if (MODE == 0) d_qbuf[idx] = phi(c * QSCALE);
                else if (MODE == 1) d_kbuf[idx] = phi(c);
                else d_vbuf[idx] = c;
            }
        }
    }
}

// ---------------- gate:  g[bh][t] = sigmoid(x[m] . Wg[h] + bg[h]) -----------
__global__ __launch_bounds__(256) void gate_kernel(const float* __restrict__ x,
                                                   const float* __restrict__ Wg,
                                                   const float* __restrict__ bg) {
    const int warp = (blockIdx.x * blockDim.x + threadIdx.x) >> 5;  // row m
    const int lane = threadIdx.x & 31;
    if (warp >= MROWS) return;

    const float4* xr = (const float4*)(x + (size_t)warp * DMODEL);
    float4 xv[8];
#pragma unroll
    for (int i = 0; i < 8; i++) xv[i] = xr[lane + i * 32];

    const int b = warp >> 11;
    const int t = warp & 2047;

    for (int h = 0; h < NHEADS; h++) {
        const float4* wr = (const float4*)(Wg + (size_t)h * DMODEL);
        float acc = 0.0f;
#pragma unroll
        for (int i = 0; i < 8; i++) {
            float4 wv = wr[lane + i * 32];
            acc = fmaf(xv[i].x, wv.x, acc);
            acc = fmaf(xv[i].y, wv.y, acc);
            acc = fmaf(xv[i].z, wv.z, acc);
            acc = fmaf(xv[i].w, wv.w, acc);
        }
#pragma unroll
        for (int off = 16; off > 0; off >>= 1)
            acc += __shfl_xor_sync(0xFFFFFFFFu, acc, off);
        if (lane == 0) {
            float z = acc + bg[h];
            d_gbuf[(size_t)(b * NHEADS + h) * SEQ + t] = 1.0f / (1.0f + __expf(-z));
        }
    }
}

// ---------------- sequential gated scan per (b,h) ---------------------------
// Block = one (b,h). 256 threads: thread (seg,j), seg=tid>>6 (0..3), j=tid&63.
// Thread owns S[i0..i0+16)[j] in registers (i0 = seg*16).
// Per step: S[i][j] = g*S[i][j] + k[i]*v[j];  y[j] = sum_i q[i]*S[i][j].
__global__ __launch_bounds__(256) void scan_kernel() {
    const int bh = blockIdx.x;
    const int tid = threadIdx.x;
    const int j = tid & 63;
    const int seg = tid >> 6;
    const int i0 = seg * 16;

    __shared__ float ksh[64];
    __shared__ float qsh[64];
    __shared__ float ypart[4][64];

    float S[16];
#pragma unroll
    for (int ii = 0; ii < 16; ii++) S[ii] = 0.0f;

    const float* kb = d_kbuf + (size_t)bh * SEQ * DHEAD;
    const float* qb = d_qbuf + (size_t)bh * SEQ * DHEAD;
    const float* vb = d_vbuf + (size_t)bh * SEQ * DHEAD;
    const float* gb = d_gbuf + (size_t)bh * SEQ;

    const int b = bh >> 4;
    const int h = bh & 15;
    float* ybase = d_ybuf + (size_t)(b * SEQ) * DMODEL + h * DHEAD + j;

    // prefetch step 0
    float kr = kb[j];
    float qr = qb[j];
    float vr = vb[j];
    float gr = gb[0];

    for (int t = 0; t < SEQ; t++) {
        if (seg == 0) ksh[j] = kr;
        if (seg == 1) qsh[j] = qr;
        const float vj = vr;
        const float gt = gr;
        __syncthreads();

        if (t + 1 < SEQ) {   // prefetch next step (overlaps compute)
            kr = kb[(size_t)(t + 1) * DHEAD + j];
            qr = qb[(size_t)(t + 1) * DHEAD + j];
            vr = vb[(size_t)(t + 1) * DHEAD + j];
            gr = gb[t + 1];
        }

        float acc0 = 0.0f, acc1 = 0.0f;
#pragma unroll
        for (int ii = 0; ii < 16; ii++) {
            float kv = ksh[i0 + ii];
            S[ii] = fmaf(kv, vj, gt * S[ii]);
            if (ii & 1) acc1 = fmaf(qsh[i0 + ii], S[ii], acc1);
            else        acc0 = fmaf(qsh[i0 + ii], S[ii], acc0);
        }
        ypart[seg][j] = acc0 + acc1;
        __syncthreads();

        if (seg == 0) {
            float yv = ypart[0][j] + ypart[1][j] + ypart[2][j] + ypart[3][j];
            ybase[(size_t)t * DMODEL] = yv;
        }
    }
}

// ---------------- launch ----------------------------------------------------
extern "C" void kernel_launch(void* const* d_in, const int* in_sizes, int n_in,
                              void* d_out, int out_size) {
    const float* x  = (const float*)d_in[0];
    const float* Wq = (const float*)d_in[1];
    const float* Wk = (const float*)d_in[2];
    const float* Wv = (const float*)d_in[3];
    const float* Wo = (const float*)d_in[4];
    const float* Wg = (const float*)d_in[5];
    const float* bg = (const float*)d_in[6];
    float* out = (float*)d_out;

    dim3 gemm_grid(DMODEL / BN, MROWS / BM);   // (8, 64)
    sgemm_kernel<0><<<gemm_grid, 256>>>(x, Wq, nullptr);
    sgemm_kernel<1><<<gemm_grid, 256>>>(x, Wk, nullptr);
    sgemm_kernel<2><<<gemm_grid, 256>>>(x, Wv, nullptr);

    gate_kernel<<<MROWS / 8, 256>>>(x, Wg, bg);   // 8 warps/block

    scan_kernel<<<NBH, 256>>>();

    sgemm_kernel<3><<<gemm_grid, 256>>>(nullptr, Wo, out);
}

// round 2
// speedup vs baseline: 1.4477x; 1.4477x over previous
#include <cuda_runtime.h>
#include <cuda_bf16.h>
#include <math.h>

// Problem constants
#define BATCH   4
#define SEQ     2048
#define DMODEL  1024
#define NHEADS  16
#define DHEAD   64
#define MROWS   (BATCH * SEQ)         // 8192
#define NBH     (BATCH * NHEADS)      // 64
#define QSCALE  0.125f                // 1/sqrt(64)

// ---------------- scratch (static device allocations; no runtime alloc) -----
__device__ float d_qbuf[NBH * SEQ * DHEAD];   // [bh][t][d]
__device__ float d_kbuf[NBH * SEQ * DHEAD];
__device__ float d_vbuf[NBH * SEQ * DHEAD];
__device__ float d_gbuf[NBH * SEQ];           // [bh][t]
__device__ float d_ybuf[MROWS * DMODEL];      // [m][n], n = h*64+d

__device__ __forceinline__ float phi(float x) {   // elu(x)+1
    return x > 0.0f ? x + 1.0f : __expf(x);
}

__device__ __forceinline__ unsigned f2tf32(float f) {
    unsigned r;
    asm("cvt.rna.tf32.f32 %0, %1;" : "=r"(r) : "f"(f));
    return r;
}

// ---------------- tf32 MMA GEMM:  C = A @ W^T ------------------------------
// A [8192,1024] row-major, W [1024,1024] row-major. BM=BN=128, BK=16.
// 256 threads = 8 warps, warp tile 64x32 via m16n8k8 (4 mtiles x 4 ntiles).
// Smem kept [row][k] with stride 20 floats (pad) -> conflict-free frag loads.
// MODE 0: q -> phi(c*QSCALE) scatter  MODE 1: k -> phi(c)
// MODE 2: v -> c scatter              MODE 3: out proj from d_ybuf -> Cout
#define KSTRIDE 20      // 16 + 4 pad

template<int MODE>
__global__ __launch_bounds__(256) void mma_gemm(const float* __restrict__ X,
                                                const float* __restrict__ W,
                                                float* __restrict__ Cout) {
    const float* A = (MODE == 3) ? d_ybuf : X;

    __shared__ unsigned As[2][128 * KSTRIDE];   // 10.24 KB each
    __shared__ unsigned Bs[2][128 * KSTRIDE];

    const int tid = threadIdx.x;
    const int bm = blockIdx.y * 128;
    const int bn = blockIdx.x * 128;

    const int warp = tid >> 5;
    const int lane = tid & 31;
    const int g   = lane >> 2;       // 0..7
    const int tig = lane & 3;        // 0..3
    const int warp_m = (warp >> 2) * 64;   // 0 or 64
    const int warp_n = (warp & 3) * 32;    // 0,32,64,96

    // global load mapping: thread -> (row, k-half)
    const int row = tid >> 1;                 // 0..127
    const int kh  = (tid & 1) * 8;            // 0 or 8
    const float* ap = A + (size_t)(bm + row) * DMODEL + kh;
    const float* wp = W + (size_t)(bn + row) * DMODEL + kh;

    float acc[4][4][4];
#pragma unroll
    for (int mt = 0; mt < 4; mt++)
#pragma unroll
        for (int nt = 0; nt < 4; nt++)
#pragma unroll
            for (int e = 0; e < 4; e++) acc[mt][nt][e] = 0.0f;

    // prologue: load tile 0
    float4 pa0 = *(const float4*)(ap);
    float4 pa1 = *(const float4*)(ap + 4);
    float4 pb0 = *(const float4*)(wp);
    float4 pb1 = *(const float4*)(wp + 4);
    {
        unsigned* d = &As[0][row * KSTRIDE + kh];
        ((uint4*)d)[0] = make_uint4(f2tf32(pa0.x), f2tf32(pa0.y), f2tf32(pa0.z), f2tf32(pa0.w));
        ((uint4*)d)[1] = make_uint4(f2tf32(pa1.x), f2tf32(pa1.y), f2tf32(pa1.z), f2tf32(pa1.w));
        unsigned* e = &Bs[0][row * KSTRIDE + kh];
        ((uint4*)e)[0] = make_uint4(f2tf32(pb0.x), f2tf32(pb0.y), f2tf32(pb0.z), f2tf32(pb0.w));
        ((uint4*)e)[1] = make_uint4(f2tf32(pb1.x), f2tf32(pb1.y), f2tf32(pb1.z), f2tf32(pb1.w));
    }
    __syncthreads();

    int buf = 0;
    const int NTILES = DMODEL / 16;   // 64
    for (int kt = 1; kt <= NTILES; kt++) {
        // prefetch next tile into registers (in flight during compute)
        if (kt < NTILES) {
            pa0 = *(const float4*)(ap + kt * 16);
            pa1 = *(const float4*)(ap + kt * 16 + 4);
            pb0 = *(const float4*)(wp + kt * 16);
            pb1 = *(const float4*)(wp + kt * 16 + 4);
        }

        // compute on current buffer: 2 k-steps of 8
        const unsigned* Ab = &As[buf][0];
        const unsigned* Bb = &Bs[buf][0];
#pragma unroll
        for (int k8 = 0; k8 < 16; k8 += 8) {
            unsigned af[4][4], bf[4][2];
#pragma unroll
            for (int mt = 0; mt < 4; mt++) {
                const int base = (warp_m + mt * 16 + g) * KSTRIDE + k8 + tig;
                af[mt][0] = Ab[base];
                af[mt][1] = Ab[base + 8 * KSTRIDE];
                af[mt][2] = Ab[base + 4];
                af[mt][3] = Ab[base + 8 * KSTRIDE + 4];
            }
#pragma unroll
            for (int nt = 0; nt < 4; nt++) {
                const int base = (warp_n + nt * 8 + g) * KSTRIDE + k8 + tig;
                bf[nt][0] = Bb[base];
                bf[nt][1] = Bb[base + 4];
            }
#pragma unroll
            for (int mt = 0; mt < 4; mt++)
#pragma unroll
                for (int nt = 0; nt < 4; nt++) {
                    asm volatile(
                        "mma.sync.aligned.m16n8k8.row.col.f32.tf32.tf32.f32 "
                        "{%0,%1,%2,%3}, {%4,%5,%6,%7}, {%8,%9}, {%0,%1,%2,%3};"
                        : "+f"(acc[mt][nt][0]), "+f"(acc[mt][nt][1]),
                          "+f"(acc[mt][nt][2]), "+f"(acc[mt][nt][3])
                        : "r"(af[mt][0]), "r"(af[mt][1]), "r"(af[mt][2]), "r"(af[mt][3]),
                          "r"(bf[nt][0]), "r"(bf[nt][1]));
                }
        }

        // store prefetched tile into other buffer
        if (kt < NTILES) {
            const int nbuf = buf ^ 1;
            unsigned* d = &As[nbuf][row * KSTRIDE + kh];
            ((uint4*)d)[0] = make_uint4(f2tf32(pa0.x), f2tf32(pa0.y), f2tf32(pa0.z), f2tf32(pa0.w));
            ((uint4*)d)[1] = make_uint4(f2tf32(pa1.x), f2tf32(pa1.y), f2tf32(pa1.z), f2tf32(pa1.w));
            unsigned* e = &Bs[nbuf][row * KSTRIDE + kh];
            ((uint4*)e)[0] = make_uint4(f2tf32(pb0.x), f2tf32(pb0.y), f2tf32(pb0.z), f2tf32(pb0.w));
            ((uint4*)e)[1] = make_uint4(f2tf32(pb1.x), f2tf32(pb1.y), f2tf32(pb1.z), f2tf32(pb1.w));
        }
        __syncthreads();
        buf ^= 1;
    }

    // epilogue
#pragma unroll
    for (int mt = 0; mt < 4; mt++) {
#pragma unroll
        for (int nt = 0; nt < 4; nt++) {
#pragma unroll
            for (int e = 0; e < 4; e++) {
                const int m = bm + warp_m + mt * 16 + g + ((e >= 2) ? 8 : 0);
                const int n = bn + warp_n + nt * 8 + 2 * tig + (e & 1);
                float c = acc[mt][nt][e];
                if (MODE == 3) {
                    Cout[(size_t)m * DMODEL + n] = c;
                } else {
                    const int b = m >> 11;
                    const int t = m & 2047;
                    const int h = n >> 6;
                    const int d = n & 63;
                    const size_t idx = ((size_t)(b * NHEADS + h) * SEQ + t) * DHEAD + d;
                    if (MODE == 0)      d_qbuf[idx] = phi(c * QSCALE);
                    else if (MODE == 1) d_kbuf[idx] = phi(c);
                    else                d_vbuf[idx] = c;
                }
            }
        }
    }
}

// ---------------- gate:  g[bh][t] = sigmoid(x[m] . Wg[h] + bg[h]) -----------
__global__ __launch_bounds__(256) void gate_kernel(const float* __restrict__ x,
                                                   const float* __restrict__ Wg,
                                                   const float* __restrict__ bg) {
    const int warp = (blockIdx.x * blockDim.x + threadIdx.x) >> 5;  // row m
    const int lane = threadIdx.x & 31;
    if (warp >= MROWS) return;

    const float4* xr = (const float4*)(x + (size_t)warp * DMODEL);
    float4 xv[8];
#pragma unroll
    for (int i = 0; i < 8; i++) xv[i] = xr[lane + i * 32];

    const int b = warp >> 11;
    const int t = warp & 2047;

    for (int h = 0; h < NHEADS; h++) {
        const float4* wr = (const float4*)(Wg + (size_t)h * DMODEL);
        float acc = 0.0f;
#pragma unroll
        for (int i = 0; i < 8; i++) {
            float4 wv = wr[lane + i * 32];
            acc = fmaf(xv[i].x, wv.x, acc);
            acc = fmaf(xv[i].y, wv.y, acc);
            acc = fmaf(xv[i].z, wv.z, acc);
            acc = fmaf(xv[i].w, wv.w, acc);
        }
#pragma unroll
        for (int off = 16; off > 0; off >>= 1)
            acc += __shfl_xor_sync(0xFFFFFFFFu, acc, off);
        if (lane == 0) {
            float z = acc + bg[h];
            d_gbuf[(size_t)(b * NHEADS + h) * SEQ + t] = 1.0f / (1.0f + __expf(-z));
        }
    }
}

// ---------------- sequential gated scan per (b,h) ---------------------------
__global__ __launch_bounds__(256) void scan_kernel() {
    const int bh = blockIdx.x;
    const int tid = threadIdx.x;
    const int j = tid & 63;
    const int seg = tid >> 6;
    const int i0 = seg * 16;

    __shared__ float ksh[64];
    __shared__ float qsh[64];
    __shared__ float ypart[4][64];

    float S[16];
#pragma unroll
    for (int ii = 0; ii < 16; ii++) S[ii] = 0.0f;

    const float* kb = d_kbuf + (size_t)bh * SEQ * DHEAD;
    const float* qb = d_qbuf + (size_t)bh * SEQ * DHEAD;
    const float* vb = d_vbuf + (size_t)bh * SEQ * DHEAD;
    const float* gb = d_gbuf + (size_t)bh * SEQ;

    const int b = bh >> 4;
    const int h = bh & 15;
    float* ybase = d_ybuf + (size_t)(b * SEQ) * DMODEL + h * DHEAD + j;

    float kr = kb[j];
    float qr = qb[j];
    float vr = vb[j];
    float gr = gb[0];

    for (int t = 0; t < SEQ; t++) {
        if (seg == 0) ksh[j] = kr;
        if (seg == 1) qsh[j] = qr;
        const float vj = vr;
        const float gt = gr;
        __syncthreads();

        if (t + 1 < SEQ) {
            kr = kb[(size_t)(t + 1) * DHEAD + j];
            qr = qb[(size_t)(t + 1) * DHEAD + j];
            vr = vb[(size_t)(t + 1) * DHEAD + j];
            gr = gb[t + 1];
        }

        float acc0 = 0.0f, acc1 = 0.0f;
#pragma unroll
        for (int ii = 0; ii < 16; ii++) {
            float kv = ksh[i0 + ii];
            S[ii] = fmaf(kv, vj, gt * S[ii]);
            if (ii & 1) acc1 = fmaf(qsh[i0 + ii], S[ii], acc1);
            else        acc0 = fmaf(qsh[i0 + ii], S[ii], acc0);
        }
        ypart[seg][j] = acc0 + acc1;
        __syncthreads();

        if (seg == 0) {
            float yv = ypart[0][j] + ypart[1][j] + ypart[2][j] + ypart[3][j];
            ybase[(size_t)t * DMODEL] = yv;
        }
    }
}

// ---------------- launch ----------------------------------------------------
extern "C" void kernel_launch(void* const* d_in, const int* in_sizes, int n_in,
                              void* d_out, int out_size) {
    const float* x  = (const float*)d_in[0];
    const float* Wq = (const float*)d_in[1];
    const float* Wk = (const float*)d_in[2];
    const float* Wv = (const float*)d_in[3];
    const float* Wo = (const float*)d_in[4];
    const float* Wg = (const float*)d_in[5];
    const float* bg = (const float*)d_in[6];
    float* out = (float*)d_out;

    dim3 gemm_grid(DMODEL / 128, MROWS / 128);   // (8, 64)
    mma_gemm<0><<<gemm_grid, 256>>>(x, Wq, nullptr);
    mma_gemm<1><<<gemm_grid, 256>>>(x, Wk, nullptr);
    mma_gemm<2><<<gemm_grid, 256>>>(x, Wv, nullptr);

    gate_kernel<<<MROWS / 8, 256>>>(x, Wg, bg);

    scan_kernel<<<NBH, 256>>>();

    mma_gemm<3><<<gemm_grid, 256>>>(nullptr, Wo, out);
}

// round 6
// speedup vs baseline: 1.7843x; 1.2325x over previous
#include <cuda_runtime.h>
#include <cuda_bf16.h>
#include <math.h>
#include <stdint.h>

#define BATCH   4
#define SEQ     2048
#define DMODEL  1024
#define NHEADS  16
#define DHEAD   64
#define MROWS   (BATCH * SEQ)         // 8192
#define NBH     (BATCH * NHEADS)      // 64
#define QSCALE  0.125f

// ---------------- scratch (static device arrays; no runtime alloc) ----------
__device__ float d_qbuf[NBH * SEQ * DHEAD];
__device__ float d_kbuf[NBH * SEQ * DHEAD];
__device__ float d_vbuf[NBH * SEQ * DHEAD];
__device__ float d_gbuf[NBH * SEQ];
__device__ float d_ybuf[MROWS * DMODEL];

__device__ __forceinline__ float phi(float x) {   // elu(x)+1
    return x > 0.0f ? x + 1.0f : __expf(x);
}

__device__ __forceinline__ unsigned f2tf32(float f) {
    unsigned r;
    asm("cvt.rna.tf32.f32 %0, %1;" : "=r"(r) : "f"(f));
    return r;
}

__device__ __forceinline__ uint32_t smem_u32(const void* p) {
    uint32_t a;
    asm("{ .reg .u64 t; cvta.to.shared.u64 t, %1; cvt.u32.u64 %0, t; }" : "=r"(a) : "l"(p));
    return a;
}

#define LDSM4(r0, r1, r2, r3, addr)                                            \
    asm volatile("ldmatrix.sync.aligned.m8n8.x4.shared.b16 {%0,%1,%2,%3}, [%4];" \
        : "=r"(r0), "=r"(r1), "=r"(r2), "=r"(r3) : "r"(addr))

// ---------------- tf32 MMA GEMM:  C = A @ W^T -------------------------------
// BM=BN=128, BK=16, 256 threads = 8 warps, warp tile 64x32 (4x4 m16n8k8).
// Smem [row][k] stride 20 (pad) -> conflict-free ldmatrix phases.
// Fragments via ldmatrix.x4.b16 (tf32 = 2x b16): A 4 LDSM + B 2 LDSM per k8.
#define KSTRIDE 20
#define SMMAT  (128 * KSTRIDE)     // elems per matrix per buffer

template<int MODE>
__global__ __launch_bounds__(256, 2) void mma_gemm(const float* __restrict__ X,
                                                   const float* __restrict__ W,
                                                   float* __restrict__ Cout) {
    const float* A = (MODE == 3) ? d_ybuf : X;

    __shared__ unsigned As[2][SMMAT];
    __shared__ unsigned Bs[2][SMMAT];

    const int tid  = threadIdx.x;
    const int bm = blockIdx.y * 128;
    const int bn = blockIdx.x * 128;

    const int warp = tid >> 5;
    const int lane = tid & 31;
    const int g   = lane >> 2;
    const int tig = lane & 3;
    const int warp_m = (warp >> 2) * 64;
    const int warp_n = (warp & 3) * 32;

    // ldmatrix per-thread address bases (element units)
    const int sub = lane >> 3;           // 0..3 (matrix group)
    const int r8  = lane & 7;
    // A: groups {rows+0,k8}, {rows+8,k8}, {rows+0,k8+4}, {rows+8,k8+4}
    const int aoff = (warp_m + (sub & 1) * 8 + r8) * KSTRIDE + (sub >> 1) * 4;
    // B: groups {rows+0,k8}, {rows+0,k8+4}, {rows+8,k8}, {rows+8,k8+4}
    const int boff = (warp_n + (sub >> 1) * 8 + r8) * KSTRIDE + (sub & 1) * 4;

    const uint32_t As_u = smem_u32(&As[0][0]);
    const uint32_t Bs_u = smem_u32(&Bs[0][0]);

    // global load mapping
    const int row = tid >> 1;
    const int kh  = (tid & 1) * 8;
    const float* ap = A + (size_t)(bm + row) * DMODEL + kh;
    const float* wp = W + (size_t)(bn + row) * DMODEL + kh;

    float acc[4][4][4];
#pragma unroll
    for (int mt = 0; mt < 4; mt++)
#pragma unroll
        for (int nt = 0; nt < 4; nt++)
#pragma unroll
            for (int e = 0; e < 4; e++) acc[mt][nt][e] = 0.0f;

    // prologue
    float4 pa0 = *(const float4*)(ap);
    float4 pa1 = *(const float4*)(ap + 4);
    float4 pb0 = *(const float4*)(wp);
    float4 pb1 = *(const float4*)(wp + 4);
    {
        unsigned* d = &As[0][row * KSTRIDE + kh];
        ((uint4*)d)[0] = make_uint4(f2tf32(pa0.x), f2tf32(pa0.y), f2tf32(pa0.z), f2tf32(pa0.w));
        ((uint4*)d)[1] = make_uint4(f2tf32(pa1.x), f2tf32(pa1.y), f2tf32(pa1.z), f2tf32(pa1.w));
        unsigned* e = &Bs[0][row * KSTRIDE + kh];
        ((uint4*)e)[0] = make_uint4(f2tf32(pb0.x), f2tf32(pb0.y), f2tf32(pb0.z), f2tf32(pb0.w));
        ((uint4*)e)[1] = make_uint4(f2tf32(pb1.x), f2tf32(pb1.y), f2tf32(pb1.z), f2tf32(pb1.w));
    }
    __syncthreads();

    int buf = 0;
    const int NTILES = DMODEL / 16;   // 64
    for (int kt = 1; kt <= NTILES; kt++) {
        if (kt < NTILES) {
            pa0 = *(const float4*)(ap + kt * 16);
            pa1 = *(const float4*)(ap + kt * 16 + 4);
            pb0 = *(const float4*)(wp + kt * 16);
            pb1 = *(const float4*)(wp + kt * 16 + 4);
        }

        const uint32_t Ab = As_u + (buf * SMMAT) * 4;
        const uint32_t Bb = Bs_u + (buf * SMMAT) * 4;
#pragma unroll
        for (int k8 = 0; k8 < 16; k8 += 8) {
            unsigned af[4][4], bf[4][2];
#pragma unroll
            for (int mt = 0; mt < 4; mt++)
                LDSM4(af[mt][0], af[mt][1], af[mt][2], af[mt][3],
                      Ab + (aoff + mt * 16 * KSTRIDE + k8) * 4);
#pragma unroll
            for (int p = 0; p < 2; p++)
                LDSM4(bf[2 * p][0], bf[2 * p][1], bf[2 * p + 1][0], bf[2 * p + 1][1],
                      Bb + (boff + p * 16 * KSTRIDE + k8) * 4);
#pragma unroll
            for (int mt = 0; mt < 4; mt++)
#pragma unroll
                for (int nt = 0; nt < 4; nt++) {
                    asm volatile(
                        "mma.sync.aligned.m16n8k8.row.col.f32.tf32.tf32.f32 "
                        "{%0,%1,%2,%3}, {%4,%5,%6,%7}, {%8,%9}, {%0,%1,%2,%3};"
                        : "+f"(acc[mt][nt][0]), "+f"(acc[mt][nt][1]),
                          "+f"(acc[mt][nt][2]), "+f"(acc[mt][nt][3])
                        : "r"(af[mt][0]), "r"(af[mt][1]), "r"(af[mt][2]), "r"(af[mt][3]),
                          "r"(bf[nt][0]), "r"(bf[nt][1]));
                }
        }

        if (kt < NTILES) {
            const int nb = buf ^ 1;
            unsigned* d = &As[nb][row * KSTRIDE + kh];
            ((uint4*)d)[0] = make_uint4(f2tf32(pa0.x), f2tf32(pa0.y), f2tf32(pa0.z), f2tf32(pa0.w));
            ((uint4*)d)[1] = make_uint4(f2tf32(pa1.x), f2tf32(pa1.y), f2tf32(pa1.z), f2tf32(pa1.w));
            unsigned* e = &Bs[nb][row * KSTRIDE + kh];
            ((uint4*)e)[0] = make_uint4(f2tf32(pb0.x), f2tf32(pb0.y), f2tf32(pb0.z), f2tf32(pb0.w));
            ((uint4*)e)[1] = make_uint4(f2tf32(pb1.x), f2tf32(pb1.y), f2tf32(pb1.z), f2tf32(pb1.w));
        }
        __syncthreads();
        buf ^= 1;
    }

    // epilogue (same as R2's passing version)
#pragma unroll
    for (int mt = 0; mt < 4; mt++) {
#pragma unroll
        for (int nt = 0; nt < 4; nt++) {
#pragma unroll
            for (int e = 0; e < 4; e++) {
                const int m = bm + warp_m + mt * 16 + g + ((e >= 2) ? 8 : 0);
                const int n = bn + warp_n + nt * 8 + 2 * tig + (e & 1);
                float c = acc[mt][nt][e];
                if (MODE == 3) {
                    Cout[(size_t)m * DMODEL + n] = c;
                } else {
                    const int b = m >> 11;
                    const int t = m & 2047;
                    const int h = n >> 6;
                    const int d = n & 63;
                    const size_t idx = ((size_t)(b * NHEADS + h) * SEQ + t) * DHEAD + d;
                    if (MODE == 0)      d_qbuf[idx] = phi(c * QSCALE);
                    else if (MODE == 1) d_kbuf[idx] = phi(c);
                    else                d_vbuf[idx] = c;
                }
            }
        }
    }
}

// ---------------- gate ------------------------------------------------------
__global__ __launch_bounds__(256) void gate_kernel(const float* __restrict__ x,
                                                   const float* __restrict__ Wg,
                                                   const float* __restrict__ bg) {
    const int warp = (blockIdx.x * blockDim.x + threadIdx.x) >> 5;
    const int lane = threadIdx.x & 31;
    if (warp >= MROWS) return;

    const float4* xr = (const float4*)(x + (size_t)warp * DMODEL);
    float4 xv[8];
#pragma unroll
    for (int i = 0; i < 8; i++) xv[i] = xr[lane + i * 32];

    const int b = warp >> 11;
    const int t = warp & 2047;

    for (int h = 0; h < NHEADS; h++) {
        const float4* wr = (const float4*)(Wg + (size_t)h * DMODEL);
        float acc = 0.0f;
#pragma unroll
        for (int i = 0; i < 8; i++) {
            float4 wv = wr[lane + i * 32];
            acc = fmaf(xv[i].x, wv.x, acc);
            acc = fmaf(xv[i].y, wv.y, acc);
            acc = fmaf(xv[i].z, wv.z, acc);
            acc = fmaf(xv[i].w, wv.w, acc);
        }
#pragma unroll
        for (int off = 16; off > 0; off >>= 1)
            acc += __shfl_xor_sync(0xFFFFFFFFu, acc, off);
        if (lane == 0) {
            float z = acc + bg[h];
            d_gbuf[(size_t)(b * NHEADS + h) * SEQ + t] = 1.0f / (1.0f + __expf(-z));
        }
    }
}

// ---------------- gated scan: 1 barrier per timestep ------------------------
// Block = one (b,h). Double-buffered ksh/qsh/ypart; y output delayed 1 step.
__global__ __launch_bounds__(256) void scan_kernel() {
    const int bh = blockIdx.x;
    const int tid = threadIdx.x;
    const int j = tid & 63;
    const int seg = tid >> 6;
    const int i0 = seg * 16;

    __shared__ float ksh[2][64];
    __shared__ float qsh[2][64];
    __shared__ float ypart[2][4][64];

    float S[16];
#pragma unroll
    for (int ii = 0; ii < 16; ii++) S[ii] = 0.0f;

    const float* kb = d_kbuf + (size_t)bh * SEQ * DHEAD;
    const float* qb = d_qbuf + (size_t)bh * SEQ * DHEAD;
    const float* vb = d_vbuf + (size_t)bh * SEQ * DHEAD;
    const float* gb = d_gbuf + (size_t)bh * SEQ;

    const int b = bh >> 4;
    const int h = bh & 15;
    float* ybase = d_ybuf + (size_t)(b * SEQ) * DMODEL + h * DHEAD + j;

    float kr = kb[j];
    float qr = qb[j];
    float vr = vb[j];
    float gr = gb[0];

    for (int t = 0; t < SEQ; t++) {
        const int cb = t & 1;
        if (seg == 0) ksh[cb][j] = kr;
        if (seg == 1) qsh[cb][j] = qr;
        const float vj = vr;
        const float gt = gr;
        __syncthreads();

        // flush previous timestep's output (writes were before the sync)
        if (seg == 0 && t > 0) {
            const int pb = cb ^ 1;
            float yv = ypart[pb][0][j] + ypart[pb][1][j] + ypart[pb][2][j] + ypart[pb][3][j];
            ybase[(size_t)(t - 1) * DMODEL] = yv;
        }

        if (t + 1 < SEQ) {
            kr = kb[(size_t)(t + 1) * DHEAD + j];
            qr = qb[(size_t)(t + 1) * DHEAD + j];
            vr = vb[(size_t)(t + 1) * DHEAD + j];
            gr = gb[t + 1];
        }

        float acc0 = 0.0f, acc1 = 0.0f;
#pragma unroll
        for (int ii = 0; ii < 16; ii++) {
            float kv = ksh[cb][i0 + ii];
            S[ii] = fmaf(kv, vj, gt * S[ii]);
            if (ii & 1) acc1 = fmaf(qsh[cb][i0 + ii], S[ii], acc1);
            else        acc0 = fmaf(qsh[cb][i0 + ii], S[ii], acc0);
        }
        ypart[cb][seg][j] = acc0 + acc1;
    }
    __syncthreads();
    if (seg == 0) {
        const int pb = (SEQ - 1) & 1;
        float yv = ypart[pb][0][j] + ypart[pb][1][j] + ypart[pb][2][j] + ypart[pb][3][j];
        ybase[(size_t)(SEQ - 1) * DMODEL] = yv;
    }
}

// ---------------- launch ----------------------------------------------------
extern "C" void kernel_launch(void* const* d_in, const int* in_sizes, int n_in,
                              void* d_out, int out_size) {
    const float* x  = (const float*)d_in[0];
    const float* Wq = (const float*)d_in[1];
    const float* Wk = (const float*)d_in[2];
    const float* Wv = (const float*)d_in[3];
    const float* Wo = (const float*)d_in[4];
    const float* Wg = (const float*)d_in[5];
    const float* bg = (const float*)d_in[6];
    float* out = (float*)d_out;

    dim3 gg(DMODEL / 128, MROWS / 128);   // (8, 64)
    mma_gemm<0><<<gg, 256>>>(x, Wq, nullptr);
    mma_gemm<1><<<gg, 256>>>(x, Wk, nullptr);
    mma_gemm<2><<<gg, 256>>>(x, Wv, nullptr);

    gate_kernel<<<MROWS / 8, 256>>>(x, Wg, bg);

    scan_kernel<<<NBH, 256>>>();

    mma_gemm<3><<<gg, 256>>>(nullptr, Wo, out);
}

// round 9
// speedup vs baseline: 2.0600x; 1.1545x over previous
#include <cuda_runtime.h>
#include <cuda_fp16.h>
#include <math.h>
#include <stdint.h>

#define BATCH   4
#define SEQ     2048
#define DMODEL  1024
#define NHEADS  16
#define DHEAD   64
#define MROWS   (BATCH * SEQ)         // 8192
#define NBH     (BATCH * NHEADS)      // 64
#define QSCALE  0.125f

// ---------------- scratch (static device arrays; no runtime alloc) ----------
__device__ float  d_qbuf[NBH * SEQ * DHEAD];
__device__ float  d_kbuf[NBH * SEQ * DHEAD];
__device__ float  d_vbuf[NBH * SEQ * DHEAD];
__device__ float  d_gbuf[NBH * SEQ];
__device__ __half d_xh[MROWS * DMODEL];            // x in fp16
__device__ __half d_wh[4 * DMODEL * DMODEL];       // Wq,Wk,Wv,Wo in fp16
__device__ __half d_yh[MROWS * DMODEL];            // scan output y in fp16

__device__ __forceinline__ float phi(float x) {    // elu(x)+1
    return x > 0.0f ? x + 1.0f : __expf(x);
}

__device__ __forceinline__ uint32_t smem_u32(const void* p) {
    uint32_t a;
    asm("{ .reg .u64 t; cvta.to.shared.u64 t, %1; cvt.u32.u64 %0, t; }" : "=r"(a) : "l"(p));
    return a;
}

#define LDSM4(r0, r1, r2, r3, addr)                                            \
    asm volatile("ldmatrix.sync.aligned.m8n8.x4.shared.b16 {%0,%1,%2,%3}, [%4];" \
        : "=r"(r0), "=r"(r1), "=r"(r2), "=r"(r3) : "r"(addr))

// ---------------- fp16 MMA GEMM:  C = A @ W^T -------------------------------
// A [8192,1024] half, W [1024,1024] half (row-major, K contiguous).
// BM=BN=128, BK=32 halves, 256 threads = 8 warps, warp tile 64x32 via
// m16n8k16 (4 mtiles x 4 ntiles). Smem [row][k] stride KSH=40 halves (pad):
// ldmatrix row starts 80B apart -> all 8 16B groups distinct -> conflict-free.
#define KSH    40
#define SMELEM (128 * KSH)            // halves per matrix per buffer

template<int MODE>
__global__ __launch_bounds__(256, 2) void mma_gemm(const __half* __restrict__ W,
                                                   float* __restrict__ Cout) {
    const __half* A = (MODE == 3) ? d_yh : d_xh;

    __shared__ __half As[2][SMELEM];   // 10 KB each
    __shared__ __half Bs[2][SMELEM];

    const int tid  = threadIdx.x;
    const int bm = blockIdx.y * 128;
    const int bn = blockIdx.x * 128;

    const int warp = tid >> 5;
    const int lane = tid & 31;
    const int g   = lane >> 2;
    const int tig = lane & 3;
    const int warp_m = (warp >> 2) * 64;
    const int warp_n = (warp & 3) * 32;

    // ldmatrix per-thread row addresses (element = half units)
    const int sub = lane >> 3;           // matrix index 0..3
    const int r8  = lane & 7;
    // A matrices: m0 rows+0/k0-7, m1 rows+8/k0-7, m2 rows+0/k8-15, m3 rows+8/k8-15
    const int aoff = (warp_m + (sub & 1) * 8 + r8) * KSH + (sub >> 1) * 8;
    // B matrices: m0 n+0..7/k0-7, m1 n+0..7/k8-15, m2 n+8..15/k0-7, m3 n+8..15/k8-15
    const int boff = (warp_n + (sub >> 1) * 8 + r8) * KSH + (sub & 1) * 8;

    const uint32_t As_u = smem_u32(&As[0][0]);
    const uint32_t Bs_u = smem_u32(&Bs[0][0]);

    // global->smem mapping: 512 chunks of 16B per tile, 2 per thread
    // chunk c: row = c>>2, o16 = c&3 (16B = 8 halves)
    const __half* ga = A + (size_t)bm * DMODEL;
    const __half* gb = W + (size_t)bn * DMODEL;

    float acc[4][4][4];
#pragma unroll
    for (int mt = 0; mt < 4; mt++)
#pragma unroll
        for (int nt = 0; nt < 4; nt++)
#pragma unroll
            for (int e = 0; e < 4; e++) acc[mt][nt][e] = 0.0f;

    const int c0 = tid, c1 = tid + 256;
    const int row0 = c0 >> 2, o0 = (c0 & 3) * 8;
    const int row1 = c1 >> 2, o1 = (c1 & 3) * 8;

    // prologue: tile 0
    uint4 va0 = *(const uint4*)(ga + (size_t)row0 * DMODEL + o0);
    uint4 va1 = *(const uint4*)(ga + (size_t)row1 * DMODEL + o1);
    uint4 vb0 = *(const uint4*)(gb + (size_t)row0 * DMODEL + o0);
    uint4 vb1 = *(const uint4*)(gb + (size_t)row1 * DMODEL + o1);
    *(uint4*)&As[0][row0 * KSH + o0] = va0;
    *(uint4*)&As[0][row1 * KSH + o1] = va1;
    *(uint4*)&Bs[0][row0 * KSH + o0] = vb0;
    *(uint4*)&Bs[0][row1 * KSH + o1] = vb1;
    __syncthreads();

    int buf = 0;
    const int NT = DMODEL / 32;       // 32 k-tiles
    for (int kt = 1; kt <= NT; kt++) {
        if (kt < NT) {
            va0 = *(const uint4*)(ga + (size_t)row0 * DMODEL + kt * 32 + o0);
            va1 = *(const uint4*)(ga + (size_t)row1 * DMODEL + kt * 32 + o1);
            vb0 = *(const uint4*)(gb + (size_t)row0 * DMODEL + kt * 32 + o0);
            vb1 = *(const uint4*)(gb + (size_t)row1 * DMODEL + kt * 32 + o1);
        }

        const uint32_t Ab = As_u + buf * (SMELEM * 2);
        const uint32_t Bb = Bs_u + buf * (SMELEM * 2);
#pragma unroll
        for (int k16 = 0; k16 < 32; k16 += 16) {
            unsigned af[4][4], bf[4][2];
#pragma unroll
            for (int mt = 0; mt < 4; mt++)
                LDSM4(af[mt][0], af[mt][1], af[mt][2], af[mt][3],
                      Ab + (aoff + mt * 16 * KSH + k16) * 2);
#pragma unroll
            for (int p = 0; p < 2; p++)
                LDSM4(bf[2 * p][0], bf[2 * p][1], bf[2 * p + 1][0], bf[2 * p + 1][1],
                      Bb + (boff + p * 16 * KSH + k16) * 2);
#pragma unroll
            for (int mt = 0; mt < 4; mt++)
#pragma unroll
                for (int nt = 0; nt < 4; nt++) {
                    asm volatile(
                        "mma.sync.aligned.m16n8k16.row.col.f32.f16.f16.f32 "
                        "{%0,%1,%2,%3}, {%4,%5,%6,%7}, {%8,%9}, {%0,%1,%2,%3};"
                        : "+f"(acc[mt][nt][0]), "+f"(acc[mt][nt][1]),
                          "+f"(acc[mt][nt][2]), "+f"(acc[mt][nt][3])
                        : "r"(af[mt][0]), "r"(af[mt][1]), "r"(af[mt][2]), "r"(af[mt][3]),
                          "r"(bf[nt][0]), "r"(bf[nt][1]));
                }
        }

        if (kt < NT) {
            const int nb = buf ^ 1;
            *(uint4*)&As[nb][row0 * KSH + o0] = va0;
            *(uint4*)&As[nb][row1 * KSH + o1] = va1;
            *(uint4*)&Bs[nb][row0 * KSH + o0] = vb0;
            *(uint4*)&Bs[nb][row1 * KSH + o1] = vb1;
        }
        __syncthreads();
        buf ^= 1;
    }

    // epilogue
#pragma unroll
    for (int mt = 0; mt < 4; mt++) {
#pragma unroll
        for (int nt = 0; nt < 4; nt++) {
#pragma unroll
            for (int e = 0; e < 4; e++) {
                const int m = bm + warp_m + mt * 16 + g + ((e >= 2) ? 8 : 0);
                const int n = bn + warp_n + nt * 8 + 2 * tig + (e & 1);
                float c = acc[mt][nt][e];
                if (MODE == 3) {
                    Cout[(size_t)m * DMODEL + n] = c;
                } else {
                    const int b = m >> 11;
                    const int t = m & 2047;
                    const int h = n >> 6;
                    const int d = n & 63;
                    const size_t idx = ((size_t)(b * NHEADS + h) * SEQ + t) * DHEAD + d;
                    if (MODE == 0)      d_qbuf[idx] = phi(c * QSCALE);
                    else if (MODE == 1) d_kbuf[idx] = phi(c);
                    else                d_vbuf[idx] = c;
                }
            }
        }
    }
}

// ---------------- fp32 -> fp16 convert --------------------------------------
// dst_sel: 0 = x, 1..4 = weight slot (sel-1). n8 = elems/8.
__global__ __launch_bounds__(256) void cvt_kernel(const float* __restrict__ src,
                                                  int dst_sel, int n8) {
    const int i = blockIdx.x * blockDim.x + threadIdx.x;
    if (i >= n8) return;
    __half* dst = (dst_sel == 0) ? d_xh
                                 : d_wh + (size_t)(dst_sel - 1) * DMODEL * DMODEL;
    const float4 v0 = ((const float4*)src)[2 * i];
    const float4 v1 = ((const float4*)src)[2 * i + 1];
    __half2 h[4];
    h[0] = __floats2half2_rn(v0.x, v0.y);
    h[1] = __floats2half2_rn(v0.z, v0.w);
    h[2] = __floats2half2_rn(v1.x, v1.y);
    h[3] = __floats2half2_rn(v1.z, v1.w);
    *(uint2*)(dst + (size_t)i * 8)     = *(uint2*)&h[0];
    *(uint2*)(dst + (size_t)i * 8 + 4) = *(uint2*)&h[2];
}

// ---------------- gate ------------------------------------------------------
__global__ __launch_bounds__(256) void gate_kernel(const float* __restrict__ x,
                                                   const float* __restrict__ Wg,
                                                   const float* __restrict__ bg) {
    const int warp = (blockIdx.x * blockDim.x + threadIdx.x) >> 5;
    const int lane = threadIdx.x & 31;
    if (warp >= MROWS) return;

    const float4* xr = (const float4*)(x + (size_t)warp * DMODEL);
    float4 xv[8];
#pragma unroll
    for (int i = 0; i < 8; i++) xv[i] = xr[lane + i * 32];

    const int b = warp >> 11;
    const int t = warp & 2047;

    for (int h = 0; h < NHEADS; h++) {
        const float4* wr = (const float4*)(Wg + (size_t)h * DMODEL);
        float acc = 0.0f;
#pragma unroll
        for (int i = 0; i < 8; i++) {
            float4 wv = wr[lane + i * 32];
            acc = fmaf(xv[i].x, wv.x, acc);
            acc = fmaf(xv[i].y, wv.y, acc);
            acc = fmaf(xv[i].z, wv.z, acc);
            acc = fmaf(xv[i].w, wv.w, acc);
        }
#pragma unroll
        for (int off = 16; off > 0; off >>= 1)
            acc += __shfl_xor_sync(0xFFFFFFFFu, acc, off);
        if (lane == 0) {
            float z = acc + bg[h];
            d_gbuf[(size_t)(b * NHEADS + h) * SEQ + t] = 1.0f / (1.0f + __expf(-z));
        }
    }
}

// ---------------- gated scan: 1 barrier per timestep ------------------------
__global__ __launch_bounds__(256) void scan_kernel() {
    const int bh = blockIdx.x;
    const int tid = threadIdx.x;
    const int j = tid & 63;
    const int seg = tid >> 6;
    const int i0 = seg * 16;

    __shared__ float ksh[2][64];
    __shared__ float qsh[2][64];
    __shared__ float ypart[2][4][64];

    float S[16];
#pragma unroll
    for (int ii = 0; ii < 16; ii++) S[ii] = 0.0f;

    const float* kb = d_kbuf + (size_t)bh * SEQ * DHEAD;
    const float* qb = d_qbuf + (size_t)bh * SEQ * DHEAD;
    const float* vb = d_vbuf + (size_t)bh * SEQ * DHEAD;
    const float* gb = d_gbuf + (size_t)bh * SEQ;

    const int b = bh >> 4;
    const int h = bh & 15;
    __half* ybase = d_yh + (size_t)(b * SEQ) * DMODEL + h * DHEAD + j;

    float kr = kb[j];
    float qr = qb[j];
    float vr = vb[j];
    float gr = gb[0];

    for (int t = 0; t < SEQ; t++) {
        const int cb = t & 1;
        if (seg == 0) ksh[cb][j] = kr;
        if (seg == 1) qsh[cb][j] = qr;
        const float vj = vr;
        const float gt = gr;
        __syncthreads();

        if (seg == 0 && t > 0) {
            const int pb = cb ^ 1;
            float yv = ypart[pb][0][j] + ypart[pb][1][j] + ypart[pb][2][j] + ypart[pb][3][j];
            ybase[(size_t)(t - 1) * DMODEL] = __float2half_rn(yv);
        }

        if (t + 1 < SEQ) {
            kr = kb[(size_t)(t + 1) * DHEAD + j];
            qr = qb[(size_t)(t + 1) * DHEAD + j];
            vr = vb[(size_t)(t + 1) * DHEAD + j];
            gr = gb[t + 1];
        }

        float acc0 = 0.0f, acc1 = 0.0f;
#pragma unroll
        for (int ii = 0; ii < 16; ii++) {
            float kv = ksh[cb][i0 + ii];
            S[ii] = fmaf(kv, vj, gt * S[ii]);
            if (ii & 1) acc1 = fmaf(qsh[cb][i0 + ii], S[ii], acc1);
            else        acc0 = fmaf(qsh[cb][i0 + ii], S[ii], acc0);
        }
        ypart[cb][seg][j] = acc0 + acc1;
    }
    __syncthreads();
    if (seg == 0) {
        const int pb = (SEQ - 1) & 1;
        float yv = ypart[pb][0][j] + ypart[pb][1][j] + ypart[pb][2][j] + ypart[pb][3][j];
        ybase[(size_t)(SEQ - 1) * DMODEL] = __float2half_rn(yv);
    }
}

// ---------------- launch ----------------------------------------------------
extern "C" void kernel_launch(void* const* d_in, const int* in_sizes, int n_in,
                              void* d_out, int out_size) {
    const float* x  = (const float*)d_in[0];
    const float* Wq = (const float*)d_in[1];
    const float* Wk = (const float*)d_in[2];
    const float* Wv = (const float*)d_in[3];
    const float* Wo = (const float*)d_in[4];
    const float* Wg = (const float*)d_in[5];
    const float* bg = (const float*)d_in[6];
    float* out = (float*)d_out;

    __half* wh_dev = nullptr;   // resolved inside kernels via d_wh; slots by index

    const int n8x = MROWS * DMODEL / 8;     // 1048576
    const int n8w = DMODEL * DMODEL / 8;    // 131072
    cvt_kernel<<<n8x / 256, 256>>>(x,  0, n8x);
    cvt_kernel<<<n8w / 256, 256>>>(Wq, 1, n8w);
    cvt_kernel<<<n8w / 256, 256>>>(Wk, 2, n8w);
    cvt_kernel<<<n8w / 256, 256>>>(Wv, 3, n8w);
    cvt_kernel<<<n8w / 256, 256>>>(Wo, 4, n8w);
    (void)wh_dev;

    // device-symbol addresses for weight slots: use offsets inside the kernel
    // via a pointer obtained from cudaGetSymbolAddress-free approach: the GEMM
    // takes the W pointer; we pass d_wh + slot*DMODEL*DMODEL resolved on device
    // side is not possible from host, so query the symbol once per launch set.
    static __half* wh_base = nullptr;
    if (!wh_base) {
        void* p = nullptr;
        cudaGetSymbolAddress(&p, d_wh);
        wh_base = (__half*)p;
    }

    dim3 gg(DMODEL / 128, MROWS / 128);   // (8, 64)
    mma_gemm<0><<<gg, 256>>>(wh_base + 0 * (size_t)DMODEL * DMODEL, nullptr);
    mma_gemm<1><<<gg, 256>>>(wh_base + 1 * (size_t)DMODEL * DMODEL, nullptr);
    mma_gemm<2><<<gg, 256>>>(wh_base + 2 * (size_t)DMODEL * DMODEL, nullptr);

    gate_kernel<<<MROWS / 8, 256>>>(x, Wg, bg);

    scan_kernel<<<NBH, 256>>>();

    mma_gemm<3><<<gg, 256>>>(wh_base + 3 * (size_t)DMODEL * DMODEL, out);
}

// round 10
// speedup vs baseline: 6.3411x; 3.0782x over previous
#include <cuda_runtime.h>
#include <cuda_fp16.h>
#include <math.h>
#include <stdint.h>

#define BATCH   4
#define SEQ     2048
#define DMODEL  1024
#define NHEADS  16
#define DHEAD   64
#define MROWS   (BATCH * SEQ)         // 8192
#define NBH     (BATCH * NHEADS)      // 64
#define QSCALE  0.125f

// ---------------- scratch (static device arrays; no runtime alloc) ----------
__device__ float  d_qbuf[NBH * SEQ * DHEAD];
__device__ float  d_kbuf[NBH * SEQ * DHEAD];
__device__ float  d_vbuf[NBH * SEQ * DHEAD];
__device__ float  d_gbuf[NBH * SEQ];
__device__ __half d_xh[MROWS * DMODEL];            // x in fp16
__device__ __half d_wh[4 * DMODEL * DMODEL];       // Wq,Wk,Wv,Wo in fp16
__device__ __half d_yh[MROWS * DMODEL];            // scan output y in fp16

__device__ __forceinline__ float phi(float x) {    // elu(x)+1
    return x > 0.0f ? x + 1.0f : __expf(x);
}

__device__ __forceinline__ uint32_t smem_u32(const void* p) {
    uint32_t a;
    asm("{ .reg .u64 t; cvta.to.shared.u64 t, %1; cvt.u32.u64 %0, t; }" : "=r"(a) : "l"(p));
    return a;
}

#define LDSM4(r0, r1, r2, r3, addr)                                            \
    asm volatile("ldmatrix.sync.aligned.m8n8.x4.shared.b16 {%0,%1,%2,%3}, [%4];" \
        : "=r"(r0), "=r"(r1), "=r"(r2), "=r"(r3) : "r"(addr))

// ---------------- fp16 MMA GEMM:  C = A @ W^T (unchanged from R6) -----------
#define KSH    40
#define SMELEM (128 * KSH)

template<int MODE>
__global__ __launch_bounds__(256, 2) void mma_gemm(const __half* __restrict__ W,
                                                   float* __restrict__ Cout) {
    const __half* A = (MODE == 3) ? d_yh : d_xh;

    __shared__ __half As[2][SMELEM];
    __shared__ __half Bs[2][SMELEM];

    const int tid  = threadIdx.x;
    const int bm = blockIdx.y * 128;
    const int bn = blockIdx.x * 128;

    const int warp = tid >> 5;
    const int lane = tid & 31;
    const int g   = lane >> 2;
    const int tig = lane & 3;
    const int warp_m = (warp >> 2) * 64;
    const int warp_n = (warp & 3) * 32;

    const int sub = lane >> 3;
    const int r8  = lane & 7;
    const int aoff = (warp_m + (sub & 1) * 8 + r8) * KSH + (sub >> 1) * 8;
    const int boff = (warp_n + (sub >> 1) * 8 + r8) * KSH + (sub & 1) * 8;

    const uint32_t As_u = smem_u32(&As[0][0]);
    const uint32_t Bs_u = smem_u32(&Bs[0][0]);

    const __half* ga = A + (size_t)bm * DMODEL;
    const __half* gb = W + (size_t)bn * DMODEL;

    float acc[4][4][4];
#pragma unroll
    for (int mt = 0; mt < 4; mt++)
#pragma unroll
        for (int nt = 0; nt < 4; nt++)
#pragma unroll
            for (int e = 0; e < 4; e++) acc[mt][nt][e] = 0.0f;

    const int c0 = tid, c1 = tid + 256;
    const int row0 = c0 >> 2, o0 = (c0 & 3) * 8;
    const int row1 = c1 >> 2, o1 = (c1 & 3) * 8;

    uint4 va0 = *(const uint4*)(ga + (size_t)row0 * DMODEL + o0);
    uint4 va1 = *(const uint4*)(ga + (size_t)row1 * DMODEL + o1);
    uint4 vb0 = *(const uint4*)(gb + (size_t)row0 * DMODEL + o0);
    uint4 vb1 = *(const uint4*)(gb + (size_t)row1 * DMODEL + o1);
    *(uint4*)&As[0][row0 * KSH + o0] = va0;
    *(uint4*)&As[0][row1 * KSH + o1] = va1;
    *(uint4*)&Bs[0][row0 * KSH + o0] = vb0;
    *(uint4*)&Bs[0][row1 * KSH + o1] = vb1;
    __syncthreads();

    int buf = 0;
    const int NT = DMODEL / 32;
    for (int kt = 1; kt <= NT; kt++) {
        if (kt < NT) {
            va0 = *(const uint4*)(ga + (size_t)row0 * DMODEL + kt * 32 + o0);
            va1 = *(const uint4*)(ga + (size_t)row1 * DMODEL + kt * 32 + o1);
            vb0 = *(const uint4*)(gb + (size_t)row0 * DMODEL + kt * 32 + o0);
            vb1 = *(const uint4*)(gb + (size_t)row1 * DMODEL + kt * 32 + o1);
        }

        const uint32_t Ab = As_u + buf * (SMELEM * 2);
        const uint32_t Bb = Bs_u + buf * (SMELEM * 2);
#pragma unroll
        for (int k16 = 0; k16 < 32; k16 += 16) {
            unsigned af[4][4], bf[4][2];
#pragma unroll
            for (int mt = 0; mt < 4; mt++)
                LDSM4(af[mt][0], af[mt][1], af[mt][2], af[mt][3],
                      Ab + (aoff + mt * 16 * KSH + k16) * 2);
#pragma unroll
            for (int p = 0; p < 2; p++)
                LDSM4(bf[2 * p][0], bf[2 * p][1], bf[2 * p + 1][0], bf[2 * p + 1][1],
                      Bb + (boff + p * 16 * KSH + k16) * 2);
#pragma unroll
            for (int mt = 0; mt < 4; mt++)
#pragma unroll
                for (int nt = 0; nt < 4; nt++) {
                    asm volatile(
                        "mma.sync.aligned.m16n8k16.row.col.f32.f16.f16.f32 "
                        "{%0,%1,%2,%3}, {%4,%5,%6,%7}, {%8,%9}, {%0,%1,%2,%3};"
                        : "+f"(acc[mt][nt][0]), "+f"(acc[mt][nt][1]),
                          "+f"(acc[mt][nt][2]), "+f"(acc[mt][nt][3])
                        : "r"(af[mt][0]), "r"(af[mt][1]), "r"(af[mt][2]), "r"(af[mt][3]),
                          "r"(bf[nt][0]), "r"(bf[nt][1]));
                }
        }

        if (kt < NT) {
            const int nb = buf ^ 1;
            *(uint4*)&As[nb][row0 * KSH + o0] = va0;
            *(uint4*)&As[nb][row1 * KSH + o1] = va1;
            *(uint4*)&Bs[nb][row0 * KSH + o0] = vb0;
            *(uint4*)&Bs[nb][row1 * KSH + o1] = vb1;
        }
        __syncthreads();
        buf ^= 1;
    }

#pragma unroll
    for (int mt = 0; mt < 4; mt++) {
#pragma unroll
        for (int nt = 0; nt < 4; nt++) {
#pragma unroll
            for (int e = 0; e < 4; e++) {
                const int m = bm + warp_m + mt * 16 + g + ((e >= 2) ? 8 : 0);
                const int n = bn + warp_n + nt * 8 + 2 * tig + (e & 1);
                float c = acc[mt][nt][e];
                if (MODE == 3) {
                    Cout[(size_t)m * DMODEL + n] = c;
                } else {
                    const int b = m >> 11;
                    const int t = m & 2047;
                    const int h = n >> 6;
                    const int d = n & 63;
                    const size_t idx = ((size_t)(b * NHEADS + h) * SEQ + t) * DHEAD + d;
                    if (MODE == 0)      d_qbuf[idx] = phi(c * QSCALE);
                    else if (MODE == 1) d_kbuf[idx] = phi(c);
                    else                d_vbuf[idx] = c;
                }
            }
        }
    }
}

// ---------------- fused fp32 -> fp16 convert (x + 4 weights, 1 launch) ------
#define NX4 (MROWS * DMODEL / 4)        // 2097152 float4 for x
#define NW4 (DMODEL * DMODEL / 4)       // 262144 float4 per weight
#define NCVT (NX4 + 4 * NW4)            // 3145728

__global__ __launch_bounds__(256) void cvt_all(const float* __restrict__ x,
                                               const float* __restrict__ wq,
                                               const float* __restrict__ wk,
                                               const float* __restrict__ wv,
                                               const float* __restrict__ wo) {
    const int i = blockIdx.x * blockDim.x + threadIdx.x;
    if (i >= NCVT) return;
    const float* src;
    __half* dst;
    size_t off;
    if (i < NX4) { src = x; dst = d_xh; off = i; }
    else {
        const int j = i - NX4;
        const int w = j >> 18;          // /262144
        off = j & (NW4 - 1);
        src = (w == 0) ? wq : (w == 1) ? wk : (w == 2) ? wv : wo;
        dst = d_wh + (size_t)w * DMODEL * DMODEL;
    }
    const float4 v = ((const float4*)src)[off];
    __half2 h0 = __floats2half2_rn(v.x, v.y);
    __half2 h1 = __floats2half2_rn(v.z, v.w);
    uint2 pkd;
    pkd.x = *(unsigned*)&h0;
    pkd.y = *(unsigned*)&h1;
    *(uint2*)(dst + off * 4) = pkd;
}

// ---------------- gate ------------------------------------------------------
__global__ __launch_bounds__(256) void gate_kernel(const float* __restrict__ x,
                                                   const float* __restrict__ Wg,
                                                   const float* __restrict__ bg) {
    const int warp = (blockIdx.x * blockDim.x + threadIdx.x) >> 5;
    const int lane = threadIdx.x & 31;
    if (warp >= MROWS) return;

    const float4* xr = (const float4*)(x + (size_t)warp * DMODEL);
    float4 xv[8];
#pragma unroll
    for (int i = 0; i < 8; i++) xv[i] = xr[lane + i * 32];

    const int b = warp >> 11;
    const int t = warp & 2047;

    for (int h = 0; h < NHEADS; h++) {
        const float4* wr = (const float4*)(Wg + (size_t)h * DMODEL);
        float acc = 0.0f;
#pragma unroll
        for (int i = 0; i < 8; i++) {
            float4 wv = wr[lane + i * 32];
            acc = fmaf(xv[i].x, wv.x, acc);
            acc = fmaf(xv[i].y, wv.y, acc);
            acc = fmaf(xv[i].z, wv.z, acc);
            acc = fmaf(xv[i].w, wv.w, acc);
        }
#pragma unroll
        for (int off = 16; off > 0; off >>= 1)
            acc += __shfl_xor_sync(0xFFFFFFFFu, acc, off);
        if (lane == 0) {
            float z = acc + bg[h];
            d_gbuf[(size_t)(b * NHEADS + h) * SEQ + t] = 1.0f / (1.0f + __expf(-z));
        }
    }
}

// ---------------- gated scan: superstep-batched, 128 blocks -----------------
// Block = (bh, jhalf): 32 state columns. Warp w owns rows [8w, 8w+8).
// SS=8 steps per superstep: cooperative coalesced loads into double-buffered
// smem; 2 __syncthreads per 8 steps; y partials reduced once per superstep.
#define SS 8

__global__ __launch_bounds__(256) void scan_kernel() {
    const int blk  = blockIdx.x;           // 0..127
    const int bh   = blk >> 1;
    const int joff = (blk & 1) * 32;
    const int tid  = threadIdx.x;
    const int w    = tid >> 5;             // warp 0..7 -> i rows [8w,8w+8)
    const int lane = tid & 31;             // j within slice

    __shared__ float ksh[2][SS][64];
    __shared__ float qsh[2][SS][64];
    __shared__ float vsh[2][SS][32];
    __shared__ float gsh[2][SS];
    __shared__ float ypart[SS][8][32];

    const float* kb = d_kbuf + (size_t)bh * SEQ * DHEAD;
    const float* qb = d_qbuf + (size_t)bh * SEQ * DHEAD;
    const float* vb = d_vbuf + (size_t)bh * SEQ * DHEAD;
    const float* gb = d_gbuf + (size_t)bh * SEQ;

    const int b = bh >> 4;
    const int h = bh & 15;
    // y output: this thread writes (step s = tid>>5, column jj = lane)
    __half* yout = d_yh + (size_t)(b * SEQ) * DMODEL + h * DHEAD + joff + lane;

    float S[8];
#pragma unroll
    for (int ii = 0; ii < 8; ii++) S[ii] = 0.0f;

    // load-assignment indices (constant per thread)
    const int kq_step = (tid & 127) >> 4;        // 0..7
    const int kq_f4   = (tid & 15) * 4;          // 0..60
    const int v_step  = tid >> 3;                // valid for tid<64
    const int v_f4    = (tid & 7) * 4;

    // prologue: prefetch superstep 0 into registers
    float4 pkq, pv;
    float  pg = 0.0f;
    pkq = (tid < 128)
        ? *(const float4*)(kb + (size_t)kq_step * DHEAD + kq_f4)
        : *(const float4*)(qb + (size_t)kq_step * DHEAD + kq_f4);
    if (tid < 64) pv = *(const float4*)(vb + (size_t)v_step * DHEAD + joff + v_f4);
    if (tid >= 64 && tid < 72) pg = gb[tid - 64];

    int buf = 0;
    for (int t0 = 0; t0 < SEQ; t0 += SS) {
        // store prefetched registers to smem[buf]
        if (tid < 128) *(float4*)&ksh[buf][kq_step][kq_f4] = pkq;
        else           *(float4*)&qsh[buf][kq_step][kq_f4] = pkq;
        if (tid < 64)  *(float4*)&vsh[buf][v_step][v_f4] = pv;
        if (tid >= 64 && tid < 72) gsh[buf][tid - 64] = pg;

        // issue loads for next superstep
        const int t1 = t0 + SS;
        if (t1 < SEQ) {
            pkq = (tid < 128)
                ? *(const float4*)(kb + (size_t)(t1 + kq_step) * DHEAD + kq_f4)
                : *(const float4*)(qb + (size_t)(t1 + kq_step) * DHEAD + kq_f4);
            if (tid < 64) pv = *(const float4*)(vb + (size_t)(t1 + v_step) * DHEAD + joff + v_f4);
            if (tid >= 64 && tid < 72) pg = gb[t1 + tid - 64];
        }
        __syncthreads();   // smem[buf] ready; previous ypart consumed

        // compute SS steps, no barriers
#pragma unroll
        for (int s = 0; s < SS; s++) {
            const float gt = gsh[buf][s];
            const float vj = vsh[buf][s][lane];
            const float4 k0 = *(const float4*)&ksh[buf][s][8 * w];
            const float4 k1 = *(const float4*)&ksh[buf][s][8 * w + 4];
            const float4 q0 = *(const float4*)&qsh[buf][s][8 * w];
            const float4 q1 = *(const float4*)&qsh[buf][s][8 * w + 4];
            float acc;
            S[0] = fmaf(k0.x, vj, gt * S[0]); acc = q0.x * S[0];
            S[1] = fmaf(k0.y, vj, gt * S[1]); acc = fmaf(q0.y, S[1], acc);
            S[2] = fmaf(k0.z, vj, gt * S[2]); acc = fmaf(q0.z, S[2], acc);
            S[3] = fmaf(k0.w, vj, gt * S[3]); acc = fmaf(q0.w, S[3], acc);
            S[4] = fmaf(k1.x, vj, gt * S[4]); acc = fmaf(q1.x, S[4], acc);
            S[5] = fmaf(k1.y, vj, gt * S[5]); acc = fmaf(q1.y, S[5], acc);
            S[6] = fmaf(k1.z, vj, gt * S[6]); acc = fmaf(q1.z, S[6], acc);
            S[7] = fmaf(k1.w, vj, gt * S[7]); acc = fmaf(q1.w, S[7], acc);
            ypart[s][w][lane] = acc;
        }
        __syncthreads();   // ypart complete

        // reduce + write y: thread handles (step = tid>>5, column = lane)
        {
            const int s = tid >> 5;
            float yv = ypart[s][0][lane] + ypart[s][1][lane]
                     + ypart[s][2][lane] + ypart[s][3][lane]
                     + ypart[s][4][lane] + ypart[s][5][lane]
                     + ypart[s][6][lane] + ypart[s][7][lane];
            yout[(size_t)(t0 + s) * DMODEL] = __float2half_rn(yv);
        }
        buf ^= 1;
    }
}

// ---------------- launch ----------------------------------------------------
extern "C" void kernel_launch(void* const* d_in, const int* in_sizes, int n_in,
                              void* d_out, int out_size) {
    const float* x  = (const float*)d_in[0];
    const float* Wq = (const float*)d_in[1];
    const float* Wk = (const float*)d_in[2];
    const float* Wv = (const float*)d_in[3];
    const float* Wo = (const float*)d_in[4];
    const float* Wg = (const float*)d_in[5];
    const float* bg = (const float*)d_in[6];
    float* out = (float*)d_out;

    void* p = nullptr;
    cudaGetSymbolAddress(&p, d_wh);
    __half* wh_base = (__half*)p;

    // launch order: cvt(1) gemm(2,3,4) gate(5) scan(6) gemm(7)
    cvt_all<<<(NCVT + 255) / 256, 256>>>(x, Wq, Wk, Wv, Wo);

    dim3 gg(DMODEL / 128, MROWS / 128);   // (8, 64)
    mma_gemm<0><<<gg, 256>>>(wh_base + 0 * (size_t)DMODEL * DMODEL, nullptr);
    mma_gemm<1><<<gg, 256>>>(wh_base + 1 * (size_t)DMODEL * DMODEL, nullptr);
    mma_gemm<2><<<gg, 256>>>(wh_base + 2 * (size_t)DMODEL * DMODEL, nullptr);

    gate_kernel<<<MROWS / 8, 256>>>(x, Wg, bg);

    scan_kernel<<<NBH * 2, 256>>>();

    mma_gemm<3><<<gg, 256>>>(wh_base + 3 * (size_t)DMODEL * DMODEL, out);
}

// round 11
// speedup vs baseline: 7.0868x; 1.1176x over previous
#include <cuda_runtime.h>
#include <cuda_fp16.h>
#include <math.h>
#include <stdint.h>

#define BATCH   4
#define SEQ     2048
#define DMODEL  1024
#define NHEADS  16
#define DHEAD   64
#define MROWS   (BATCH * SEQ)         // 8192
#define NBH     (BATCH * NHEADS)      // 64
#define QSCALE  0.125f

// ---------------- scratch (static device arrays; no runtime alloc) ----------
__device__ float  d_qbuf[NBH * SEQ * DHEAD];
__device__ float  d_kbuf[NBH * SEQ * DHEAD];
__device__ float  d_vbuf[NBH * SEQ * DHEAD];
__device__ float  d_gbuf[NBH * SEQ];
__device__ __half d_xh[MROWS * DMODEL];            // x in fp16
__device__ __half d_wh[4 * DMODEL * DMODEL];       // Wq,Wk,Wv,Wo in fp16
__device__ __half d_yh[MROWS * DMODEL];            // scan output y in fp16

__device__ __forceinline__ float phi(float x) {    // elu(x)+1
    return x > 0.0f ? x + 1.0f : __expf(x);
}

__device__ __forceinline__ uint32_t smem_u32(const void* p) {
    uint32_t a;
    asm("{ .reg .u64 t; cvta.to.shared.u64 t, %1; cvt.u32.u64 %0, t; }" : "=r"(a) : "l"(p));
    return a;
}

#define LDSM4(r0, r1, r2, r3, addr)                                            \
    asm volatile("ldmatrix.sync.aligned.m8n8.x4.shared.b16 {%0,%1,%2,%3}, [%4];" \
        : "=r"(r0), "=r"(r1), "=r"(r2), "=r"(r3) : "r"(addr))

#define CPA16(dst, src)                                                        \
    asm volatile("cp.async.cg.shared.global [%0], [%1], 16;" :: "r"(dst), "l"(src))

// ---------------- fp16 MMA GEMM:  C = A @ W^T -------------------------------
// BM=BN=128, BK=32 halves. 128 threads = 4 warps in 2x2, warp tile 64x64
// (4 mtiles x 8 ntiles of m16n8k16). cp.async 3-stage pipeline.
// Smem [row][k] stride KSH=40 halves (pad): conflict-free ldmatrix.
#define KSH     40
#define SMELEM  (128 * KSH)                 // halves per matrix per stage
#define STAGE_H (2 * SMELEM)                // A + B per stage
#define STAGE_B (STAGE_H * 2)               // bytes per stage
#define GEMM_SMEM (3 * STAGE_B)             // 61440 bytes

template<int MODE>
__global__ __launch_bounds__(128, 2) void mma_gemm(const __half* __restrict__ W,
                                                   float* __restrict__ Cout) {
    const __half* A = (MODE == 3) ? d_yh : d_xh;

    extern __shared__ __half sm[];
    const uint32_t base = smem_u32(sm);

    const int tid  = threadIdx.x;
    const int bm = blockIdx.y * 128;
    const int bn = blockIdx.x * 128;

    const int warp = tid >> 5;
    const int lane = tid & 31;
    const int g   = lane >> 2;
    const int tig = lane & 3;
    const int warp_m = (warp & 1) * 64;
    const int warp_n = (warp >> 1) * 64;

    // ldmatrix per-thread offsets (half units)
    const int sub = lane >> 3;
    const int r8  = lane & 7;
    const int aoff = (warp_m + (sub & 1) * 8 + r8) * KSH + (sub >> 1) * 8;
    const int boff = (warp_n + (sub >> 1) * 8 + r8) * KSH + (sub & 1) * 8;

    const __half* ga = A + (size_t)bm * DMODEL;
    const __half* gb = W + (size_t)bn * DMODEL;

    // cp.async chunk mapping: 512 16B-chunks per matrix, 4 per thread
    int rowc[4], oc[4];
#pragma unroll
    for (int i = 0; i < 4; i++) {
        const int c = tid + i * 128;
        rowc[i] = c >> 2;
        oc[i]   = (c & 3) * 8;
    }

    float acc[4][8][4];
#pragma unroll
    for (int mt = 0; mt < 4; mt++)
#pragma unroll
        for (int nt = 0; nt < 8; nt++)
#pragma unroll
            for (int e = 0; e < 4; e++) acc[mt][nt][e] = 0.0f;

    // issue loads for k-tile kt into stage st
    auto issue = [&](int kt, int st) {
        const uint32_t sa = base + st * STAGE_B;
        const uint32_t sb = sa + SMELEM * 2;
#pragma unroll
        for (int i = 0; i < 4; i++) {
            const uint32_t d = (uint32_t)(rowc[i] * KSH + oc[i]) * 2;
            CPA16(sa + d, ga + (size_t)rowc[i] * DMODEL + kt * 32 + oc[i]);
            CPA16(sb + d, gb + (size_t)rowc[i] * DMODEL + kt * 32 + oc[i]);
        }
        asm volatile("cp.async.commit_group;" ::: "memory");
    };

    issue(0, 0);
    issue(1, 1);

    const int NT = DMODEL / 32;    // 32
    int st = 0;
    for (int kt = 0; kt < NT; kt++) {
        if (kt < NT - 2) { asm volatile("cp.async.wait_group 1;" ::: "memory"); }
        else             { asm volatile("cp.async.wait_group 0;" ::: "memory"); }
        __syncthreads();

        if (kt + 2 < NT) {
            int st2 = st + 2; if (st2 >= 3) st2 -= 3;
            issue(kt + 2, st2);
        }

        const uint32_t Ab = base + st * STAGE_B;
        const uint32_t Bb = Ab + SMELEM * 2;
#pragma unroll
        for (int k16 = 0; k16 < 32; k16 += 16) {
            unsigned af[4][4], bf[8][2];
#pragma unroll
            for (int mt = 0; mt < 4; mt++)
                LDSM4(af[mt][0], af[mt][1], af[mt][2], af[mt][3],
                      Ab + (uint32_t)(aoff + mt * 16 * KSH + k16) * 2);
#pragma unroll
            for (int p = 0; p < 4; p++)
                LDSM4(bf[2 * p][0], bf[2 * p][1], bf[2 * p + 1][0], bf[2 * p + 1][1],
                      Bb + (uint32_t)(boff + p * 16 * KSH + k16) * 2);
#pragma unroll
            for (int mt = 0; mt < 4; mt++)
#pragma unroll
                for (int nt = 0; nt < 8; nt++) {
                    asm volatile(
                        "mma.sync.aligned.m16n8k16.row.col.f32.f16.f16.f32 "
                        "{%0,%1,%2,%3}, {%4,%5,%6,%7}, {%8,%9}, {%0,%1,%2,%3};"
                        : "+f"(acc[mt][nt][0]), "+f"(acc[mt][nt][1]),
                          "+f"(acc[mt][nt][2]), "+f"(acc[mt][nt][3])
                        : "r"(af[mt][0]), "r"(af[mt][1]), "r"(af[mt][2]), "r"(af[mt][3]),
                          "r"(bf[nt][0]), "r"(bf[nt][1]));
                }
        }
        if (++st >= 3) st -= 3;
        __syncthreads();
    }

    // epilogue
#pragma unroll
    for (int mt = 0; mt < 4; mt++) {
#pragma unroll
        for (int nt = 0; nt < 8; nt++) {
#pragma unroll
            for (int e = 0; e < 4; e++) {
                const int m = bm + warp_m + mt * 16 + g + ((e >= 2) ? 8 : 0);
                const int n = bn + warp_n + nt * 8 + 2 * tig + (e & 1);
                float c = acc[mt][nt][e];
                if (MODE == 3) {
                    Cout[(size_t)m * DMODEL + n] = c;
                } else {
                    const int b = m >> 11;
                    const int t = m & 2047;
                    const int h = n >> 6;
                    const int d = n & 63;
                    const size_t idx = ((size_t)(b * NHEADS + h) * SEQ + t) * DHEAD + d;
                    if (MODE == 0)      d_qbuf[idx] = phi(c * QSCALE);
                    else if (MODE == 1) d_kbuf[idx] = phi(c);
                    else                d_vbuf[idx] = c;
                }
            }
        }
    }
}

// ---------------- prep: x->fp16 + gate (fused), weights->fp16 ---------------
// blocks [0,1024): 8 warps, warp per x-row: cvt row + 16 gate dots.
// blocks [1024,5120): weight cvt, 256 float4 per block.
__global__ __launch_bounds__(256) void prep_kernel(const float* __restrict__ x,
                                                   const float* __restrict__ wq,
                                                   const float* __restrict__ wk,
                                                   const float* __restrict__ wv,
                                                   const float* __restrict__ wo,
                                                   const float* __restrict__ Wg,
                                                   const float* __restrict__ bg) {
    const int blk = blockIdx.x;
    const int tid = threadIdx.x;
    if (blk < 1024) {
        const int w = tid >> 5, lane = tid & 31;
        const int row = blk * 8 + w;
        const float4* xr = (const float4*)(x + (size_t)row * DMODEL);
        float4 xv[8];
#pragma unroll
        for (int i = 0; i < 8; i++) xv[i] = xr[lane + i * 32];

        __half* xd = d_xh + (size_t)row * DMODEL;
#pragma unroll
        for (int i = 0; i < 8; i++) {
            __half2 h0 = __floats2half2_rn(xv[i].x, xv[i].y);
            __half2 h1 = __floats2half2_rn(xv[i].z, xv[i].w);
            uint2 u;
            u.x = *(unsigned*)&h0;
            u.y = *(unsigned*)&h1;
            *(uint2*)(xd + (lane + i * 32) * 4) = u;
        }

        const int b = row >> 11;
        const int t = row & 2047;
        for (int h = 0; h < NHEADS; h++) {
            const float4* wr = (const float4*)(Wg + (size_t)h * DMODEL);
            float acc = 0.0f;
#pragma unroll
            for (int i = 0; i < 8; i++) {
                float4 wv = wr[lane + i * 32];
                acc = fmaf(xv[i].x, wv.x, acc);
                acc = fmaf(xv[i].y, wv.y, acc);
                acc = fmaf(xv[i].z, wv.z, acc);
                acc = fmaf(xv[i].w, wv.w, acc);
            }
#pragma unroll
            for (int off = 16; off > 0; off >>= 1)
                acc += __shfl_xor_sync(0xFFFFFFFFu, acc, off);
            if (lane == 0) {
                float z = acc + bg[h];
                d_gbuf[(size_t)(b * NHEADS + h) * SEQ + t] = 1.0f / (1.0f + __expf(-z));
            }
        }
    } else {
        const int j = blk - 1024;            // 0..4095
        const int w = j >> 10;               // matrix 0..3
        const int off = ((j & 1023) << 8) + tid;   // float4 index
        const float* src = (w == 0) ? wq : (w == 1) ? wk : (w == 2) ? wv : wo;
        const float4 v = ((const float4*)src)[off];
        __half2 h0 = __floats2half2_rn(v.x, v.y);
        __half2 h1 = __floats2half2_rn(v.z, v.w);
        uint2 u;
        u.x = *(unsigned*)&h0;
        u.y = *(unsigned*)&h1;
        *(uint2*)(d_wh + (size_t)w * DMODEL * DMODEL + (size_t)off * 4) = u;
    }
}

// ---------------- gated scan: superstep-batched, 128 blocks (R7) ------------
#define SS 8

__global__ __launch_bounds__(256) void scan_kernel() {
    const int blk  = blockIdx.x;           // 0..127
    const int bh   = blk >> 1;
    const int joff = (blk & 1) * 32;
    const int tid  = threadIdx.x;
    const int w    = tid >> 5;
    const int lane = tid & 31;

    __shared__ float ksh[2][SS][64];
    __shared__ float qsh[2][SS][64];
    __shared__ float vsh[2][SS][32];
    __shared__ float gsh[2][SS];
    __shared__ float ypart[SS][8][32];

    const float* kb = d_kbuf + (size_t)bh * SEQ * DHEAD;
    const float* qb = d_qbuf + (size_t)bh * SEQ * DHEAD;
    const float* vb = d_vbuf + (size_t)bh * SEQ * DHEAD;
    const float* gb = d_gbuf + (size_t)bh * SEQ;

    const int b = bh >> 4;
    const int h = bh & 15;
    __half* yout = d_yh + (size_t)(b * SEQ) * DMODEL + h * DHEAD + joff + lane;

    float S[8];
#pragma unroll
    for (int ii = 0; ii < 8; ii++) S[ii] = 0.0f;

    const int kq_step = (tid & 127) >> 4;
    const int kq_f4   = (tid & 15) * 4;
    const int v_step  = tid >> 3;
    const int v_f4    = (tid & 7) * 4;

    float4 pkq, pv;
    float  pg = 0.0f;
    pkq = (tid < 128)
        ? *(const float4*)(kb + (size_t)kq_step * DHEAD + kq_f4)
        : *(const float4*)(qb + (size_t)kq_step * DHEAD + kq_f4);
    if (tid < 64) pv = *(const float4*)(vb + (size_t)v_step * DHEAD + joff + v_f4);
    if (tid >= 64 && tid < 72) pg = gb[tid - 64];

    int buf = 0;
    for (int t0 = 0; t0 < SEQ; t0 += SS) {
        if (tid < 128) *(float4*)&ksh[buf][kq_step][kq_f4] = pkq;
        else           *(float4*)&qsh[buf][kq_step][kq_f4] = pkq;
        if (tid < 64)  *(float4*)&vsh[buf][v_step][v_f4] = pv;
        if (tid >= 64 && tid < 72) gsh[buf][tid - 64] = pg;

        const int t1 = t0 + SS;
        if (t1 < SEQ) {
            pkq = (tid < 128)
                ? *(const float4*)(kb + (size_t)(t1 + kq_step) * DHEAD + kq_f4)
                : *(const float4*)(qb + (size_t)(t1 + kq_step) * DHEAD + kq_f4);
            if (tid < 64) pv = *(const float4*)(vb + (size_t)(t1 + v_step) * DHEAD + joff + v_f4);
            if (tid >= 64 && tid < 72) pg = gb[t1 + tid - 64];
        }
        __syncthreads();

#pragma unroll
        for (int s = 0; s < SS; s++) {
            const float gt = gsh[buf][s];
            const float vj = vsh[buf][s][lane];
            const float4 k0 = *(const float4*)&ksh[buf][s][8 * w];
            const float4 k1 = *(const float4*)&ksh[buf][s][8 * w + 4];
            const float4 q0 = *(const float4*)&qsh[buf][s][8 * w];
            const float4 q1 = *(const float4*)&qsh[buf][s][8 * w + 4];
            float acc;
            S[0] = fmaf(k0.x, vj, gt * S[0]); acc = q0.x * S[0];
            S[1] = fmaf(k0.y, vj, gt * S[1]); acc = fmaf(q0.y, S[1], acc);
            S[2] = fmaf(k0.z, vj, gt * S[2]); acc = fmaf(q0.z, S[2], acc);
            S[3] = fmaf(k0.w, vj, gt * S[3]); acc = fmaf(q0.w, S[3], acc);
            S[4] = fmaf(k1.x, vj, gt * S[4]); acc = fmaf(q1.x, S[4], acc);
            S[5] = fmaf(k1.y, vj, gt * S[5]); acc = fmaf(q1.y, S[5], acc);
            S[6] = fmaf(k1.z, vj, gt * S[6]); acc = fmaf(q1.z, S[6], acc);
            S[7] = fmaf(k1.w, vj, gt * S[7]); acc = fmaf(q1.w, S[7], acc);
            ypart[s][w][lane] = acc;
        }
        __syncthreads();

        {
            const int s = tid >> 5;
            float yv = ypart[s][0][lane] + ypart[s][1][lane]
                     + ypart[s][2][lane] + ypart[s][3][lane]
                     + ypart[s][4][lane] + ypart[s][5][lane]
                     + ypart[s][6][lane] + ypart[s][7][lane];
            yout[(size_t)(t0 + s) * DMODEL] = __float2half_rn(yv);
        }
        buf ^= 1;
    }
}

// ---------------- launch ----------------------------------------------------
extern "C" void kernel_launch(void* const* d_in, const int* in_sizes, int n_in,
                              void* d_out, int out_size) {
    const float* x  = (const float*)d_in[0];
    const float* Wq = (const float*)d_in[1];
    const float* Wk = (const float*)d_in[2];
    const float* Wv = (const float*)d_in[3];
    const float* Wo = (const float*)d_in[4];
    const float* Wg = (const float*)d_in[5];
    const float* bg = (const float*)d_in[6];
    float* out = (float*)d_out;

    cudaFuncSetAttribute(mma_gemm<0>, cudaFuncAttributeMaxDynamicSharedMemorySize, GEMM_SMEM);
    cudaFuncSetAttribute(mma_gemm<1>, cudaFuncAttributeMaxDynamicSharedMemorySize, GEMM_SMEM);
    cudaFuncSetAttribute(mma_gemm<2>, cudaFuncAttributeMaxDynamicSharedMemorySize, GEMM_SMEM);
    cudaFuncSetAttribute(mma_gemm<3>, cudaFuncAttributeMaxDynamicSharedMemorySize, GEMM_SMEM);

    void* p = nullptr;
    cudaGetSymbolAddress(&p, d_wh);
    __half* wh_base = (__half*)p;

    prep_kernel<<<5120, 256>>>(x, Wq, Wk, Wv, Wo, Wg, bg);

    dim3 gg(DMODEL / 128, MROWS / 128);   // (8, 64)
    mma_gemm<0><<<gg, 128, GEMM_SMEM>>>(wh_base + 0 * (size_t)DMODEL * DMODEL, nullptr);
    mma_gemm<1><<<gg, 128, GEMM_SMEM>>>(wh_base + 1 * (size_t)DMODEL * DMODEL, nullptr);
    mma_gemm<2><<<gg, 128, GEMM_SMEM>>>(wh_base + 2 * (size_t)DMODEL * DMODEL, nullptr);

    scan_kernel<<<NBH * 2, 256>>>();

    mma_gemm<3><<<gg, 128, GEMM_SMEM>>>(wh_base + 3 * (size_t)DMODEL * DMODEL, out);
}